// round 15
// baseline (speedup 1.0000x reference)
#include <cuda_runtime.h>
#include <cuda_fp16.h>
#include <cstdint>
#include <math.h>

// Shapes (fixed by the problem)
#define Bc 2
#define Tc 2048
#define Sc 2048
#define Cc 1024
#define Hc 16
#define HDc 64
#define BHc (Bc*Hc)          // 32
#define NSPLIT 16

// ---------------- scratch (device globals; no allocation allowed) ----------------
__device__ float g_Q [Bc*Tc*Cc];                 // Q projection (fp32)
__device__ float g_KV[Bc*Sc*2*Cc];               // KV projection (fp32, raw)
__device__ float g_cos[Sc*32];
__device__ float g_sin[Sc*32];
__device__ float g_Kpart[NSPLIT][BHc*HDc];
__device__ float g_Ksum [BHc*HDc];
__device__ float g_Mpart[NSPLIT][BHc*HDc*HDc];
__device__ float g_M    [BHc*HDc*HDc];

// fp16 operands (K-major, K = 1024). Activations single; weights hi/lo split.
__device__ __half g_xh[Bc*Tc*Cc];                  // x (single fp16)
__device__ __half g_mh[Bc*Sc*Cc];                  // memory
__device__ __half g_yh[Bc*Tc*Cc];                  // attention out
__device__ __half g_kvwt_hi[2*Cc*Cc], g_kvwt_lo[2*Cc*Cc];  // kv_w^T [2048,1024]
__device__ __half g_qwt_hi [Cc*Cc],   g_qwt_lo [Cc*Cc];    // q_w^T
__device__ __half g_pwt_hi [Cc*Cc],   g_pwt_lo [Cc*Cc];    // proj_w^T

__device__ __forceinline__ float eluplus(float x) {
    return x > 0.0f ? x + 1.0f : expf(x);
}

// ================= mma.sync helpers (sm_80 baseline; safe on compute_103) =================
__device__ __forceinline__ uint32_t smem_u32(const void* p) {
    uint32_t a;
    asm("{ .reg .u64 t; cvta.to.shared.u64 t, %1; cvt.u32.u64 %0, t; }" : "=r"(a) : "l"(p));
    return a;
}
__device__ __forceinline__ void cpa16(uint32_t dst, const void* src) {
    asm volatile("cp.async.cg.shared.global [%0], [%1], 16;" :: "r"(dst), "l"(src));
}
__device__ __forceinline__ void ldsm_x4(uint32_t* r, uint32_t addr) {
    asm volatile("ldmatrix.sync.aligned.m8n8.x4.shared.b16 {%0,%1,%2,%3}, [%4];"
        : "=r"(r[0]), "=r"(r[1]), "=r"(r[2]), "=r"(r[3]) : "r"(addr));
}
__device__ __forceinline__ void mma16816h(float* c, const uint32_t* a, const uint32_t* b) {
    asm volatile("mma.sync.aligned.m16n8k16.row.col.f32.f16.f16.f32 "
        "{%0,%1,%2,%3}, {%4,%5,%6,%7}, {%8,%9}, {%0,%1,%2,%3};"
        : "+f"(c[0]), "+f"(c[1]), "+f"(c[2]), "+f"(c[3])
        : "r"(a[0]), "r"(a[1]), "r"(a[2]), "r"(a[3]), "r"(b[0]), "r"(b[1]));
}

// ================= fp16x2 HMMA GEMM: C[M,N] = A[M,K] @ (Wh+Wl)[N,K]^T + bias =================
// Tile 256x128 (MxN), BK=64, K=1024 fixed, 3-stage cp.async pipeline.
// 8 warps = 4(m) x 2(n); warp tile 64x64 (4 mf x 8 nf).
#define GBM 256
#define GBN 128
#define GBK 64
#define GK  1024
#define GNIT (GK / GBK)            // 16
#define ROWB 144                   // bytes per smem row (64 fp16 + 16 pad)
#define A_BYTES (256 * ROWB)       // 36864
#define B_BYTES (128 * ROWB)       // 18432
#define OFF_A  0
#define OFF_BH (A_BYTES)
#define OFF_BL (A_BYTES + B_BYTES)
#define STAGE_BYTES (A_BYTES + 2 * B_BYTES)   // 73728
#define NSTAGE 3
#define SM_TOTAL (NSTAGE * STAGE_BYTES)       // 221184

__global__ __launch_bounds__(256, 1)
void tc_gemm(const __half* __restrict__ A,
             const __half* __restrict__ Bh, const __half* __restrict__ Bl,
             const float* __restrict__ bias, float* __restrict__ C, int N) {
    extern __shared__ char smem[];
    const uint32_t sb = smem_u32(smem);
    const int tid = threadIdx.x, wid = tid >> 5, lane = tid & 31;
    const int wm = wid >> 1, wn = wid & 1;             // 4 x 2 warp grid
    const int m0 = blockIdx.y * GBM, n0 = blockIdx.x * GBN;

    float acc[4][8][4];
#pragma unroll
    for (int i = 0; i < 4; i++)
#pragma unroll
        for (int j = 0; j < 8; j++)
#pragma unroll
            for (int q = 0; q < 4; q++) acc[i][j][q] = 0.0f;

    // loader mapping: rows of 64 fp16 = 8 chunks of 16B.
    const int lrow = tid >> 3;             // 0..31
    const int lcol = (tid & 7) * 8;        // fp16 col offset (0..56)
    const uint32_t ldst = (uint32_t)(lrow * ROWB + (tid & 7) * 16);

    auto prefetch = [&](int it) {
        const int st = it % NSTAGE;
        const int k0 = it * GBK;
        const uint32_t base = sb + st * STAGE_BYTES;
#pragma unroll
        for (int p = 0; p < 8; p++) {      // A: 256 rows, 32 per pass
            const size_t asrc = (size_t)(m0 + lrow + 32 * p) * GK + k0 + lcol;
            cpa16(base + OFF_A + ldst + (uint32_t)(p * 32 * ROWB), A + asrc);
        }
#pragma unroll
        for (int p = 0; p < 4; p++) {      // B hi/lo: 128 rows, 32 per pass
            const size_t bsrc = (size_t)(n0 + lrow + 32 * p) * GK + k0 + lcol;
            cpa16(base + OFF_BH + ldst + (uint32_t)(p * 32 * ROWB), Bh + bsrc);
            cpa16(base + OFF_BL + ldst + (uint32_t)(p * 32 * ROWB), Bl + bsrc);
        }
        asm volatile("cp.async.commit_group;" ::: "memory");
    };

    prefetch(0); prefetch(1);

    // fragment smem addresses (relative to stage base)
    const uint32_t a_rb = (uint32_t)((wm * 64 + (lane & 15)) * ROWB + (lane >> 4) * 16);
    const uint32_t b_rb = (uint32_t)((wn * 64 + (lane & 15)) * ROWB + (lane >> 4) * 16);

    for (int it = 0; it < GNIT; it++) {
        if (it + 2 < GNIT) { asm volatile("cp.async.wait_group 1;" ::: "memory"); }
        else               { asm volatile("cp.async.wait_group 0;" ::: "memory"); }
        __syncthreads();
        if (it + 2 < GNIT) prefetch(it + 2);

        const uint32_t base = sb + (it % NSTAGE) * STAGE_BYTES;
#pragma unroll
        for (int kk = 0; kk < 4; kk++) {               // four k16 steps per BK=64
            const uint32_t koff = (uint32_t)(kk * 32);  // 16 fp16 = 32 bytes
            // B fragments: pair p covers nf(2p), nf(2p+1) in regs {r[o], r[o+2]}
            uint32_t bhf[4][4], blf[4][4];
#pragma unroll
            for (int p = 0; p < 4; p++) {
                uint32_t bd = base + b_rb + (uint32_t)(p * 16 * ROWB) + koff;
                ldsm_x4(bhf[p], bd + OFF_BH);
                ldsm_x4(blf[p], bd + OFF_BL);
            }
#pragma unroll
            for (int mf = 0; mf < 4; mf++) {
                uint32_t ad = base + a_rb + (uint32_t)(mf * 16 * ROWB) + koff;
                uint32_t af[4];
                ldsm_x4(af, ad + OFF_A);
#pragma unroll
                for (int nf = 0; nf < 8; nf++) {
                    const int p = nf >> 1, o = nf & 1;
                    uint32_t bhv[2] = {bhf[p][o], bhf[p][o + 2]};
                    uint32_t blv[2] = {blf[p][o], blf[p][o + 2]};
                    mma16816h(acc[mf][nf], af, bhv);
                    mma16816h(acc[mf][nf], af, blv);
                }
            }
        }
    }

    // epilogue: direct stores with bias
#pragma unroll
    for (int mf = 0; mf < 4; mf++) {
        const int r0 = m0 + wm * 64 + mf * 16 + (lane >> 2);
#pragma unroll
        for (int nf = 0; nf < 8; nf++) {
            const int col = n0 + wn * 64 + nf * 8 + (lane & 3) * 2;
            const float b0 = bias[col], b1 = bias[col + 1];
            float* p0 = C + (size_t)r0 * N + col;
            float2 v0 = make_float2(acc[mf][nf][0] + b0, acc[mf][nf][1] + b1);
            float2 v1 = make_float2(acc[mf][nf][2] + b0, acc[mf][nf][3] + b1);
            *(float2*)p0 = v0;
            *(float2*)(p0 + 8 * N) = v1;
        }
    }
}

// ---------------- operand preparation ----------------
// activations: fp32 -> single fp16
__global__ void act_f16_kernel(const float* __restrict__ A,
                               __half* __restrict__ H, int n4) {
    int i = blockIdx.x * 256 + threadIdx.x;
    if (i >= n4) return;
    float4 v = *(const float4*)(A + (size_t)i * 4);
    __half h[4] = {__float2half_rn(v.x), __float2half_rn(v.y),
                   __float2half_rn(v.z), __float2half_rn(v.w)};
    *(uint2*)(H + (size_t)i * 4) = *(uint2*)h;
}

// weights: transpose + fp16 hi/lo split: W[K,N] -> Wt_hi/lo[N,K]
__global__ void wtrans_split_kernel(const float* __restrict__ W,
                                    __half* __restrict__ th,
                                    __half* __restrict__ tl, int K, int N) {
    __shared__ float t[32][33];
    int k0 = blockIdx.y * 32, n0 = blockIdx.x * 32;
    int tx = threadIdx.x, ty = threadIdx.y;
#pragma unroll
    for (int i = ty; i < 32; i += 8)
        t[i][tx] = W[(size_t)(k0 + i) * N + n0 + tx];
    __syncthreads();
#pragma unroll
    for (int i = ty; i < 32; i += 8) {
        float v = t[tx][i];
        __half h = __float2half_rn(v);
        size_t o = (size_t)(n0 + i) * K + k0 + tx;
        th[o] = h;
        tl[o] = __float2half_rn(v - __half2float(h));
    }
}

// ---------------- rope cos/sin table ----------------
__global__ void rope_table_kernel() {
    int idx = blockIdx.x * blockDim.x + threadIdx.x;
    if (idx >= Sc * 32) return;
    int t = idx >> 5, j = idx & 31;
    float ex = (float)(2 * j) / 64.0f;
    float invf = 1.0f / powf(10000.0f, ex);
    float ang = (float)t * invf;
    float s, c;
    sincosf(ang, &s, &c);
    g_cos[idx] = c;
    g_sin[idx] = s;
}

// ---------------- fused: elu+rope K on the fly, Mpart = K_rot^T V, Ksum partials ----------------
__global__ __launch_bounds__(256)
void compute_mpart_kernel() {
    const int bh = blockIdx.x, split = blockIdx.y;
    const int b = bh >> 4, h = bh & 15;
    __shared__ float Ksm[32][64];
    __shared__ float Vsm[32][68];
    __shared__ float red[32][64];
    const int tid = threadIdx.x;
    const int ti = tid >> 4, td = tid & 15;
    const int lrow = tid >> 3;                  // 0..31
    const int jc = (tid & 7) * 4;               // pair-col base 0..28

    float acc[4][4];
#pragma unroll
    for (int i = 0; i < 4; i++)
#pragma unroll
        for (int j = 0; j < 4; j++) acc[i][j] = 0.0f;
    float ks1[4] = {0, 0, 0, 0}, ks2[4] = {0, 0, 0, 0};

    for (int kt = 0; kt < 4; kt++) {
        const int s = split * 128 + kt * 32 + lrow;
        const float* kp = &g_KV[(size_t)(b * Sc + s) * 2048 + h * 64];
        float4 k1 = *(const float4*)(kp + jc);
        float4 k2 = *(const float4*)(kp + jc + 32);
        float4 c4 = *(const float4*)&g_cos[s * 32 + jc];
        float4 s4 = *(const float4*)&g_sin[s * 32 + jc];
        float e1[4] = {eluplus(k1.x), eluplus(k1.y), eluplus(k1.z), eluplus(k1.w)};
        float e2[4] = {eluplus(k2.x), eluplus(k2.y), eluplus(k2.z), eluplus(k2.w)};
        float cc[4] = {c4.x, c4.y, c4.z, c4.w};
        float ss[4] = {s4.x, s4.y, s4.z, s4.w};
#pragma unroll
        for (int q = 0; q < 4; q++) {
            Ksm[lrow][jc + q]      = e1[q] * cc[q] - e2[q] * ss[q];
            Ksm[lrow][jc + 32 + q] = e2[q] * cc[q] + e1[q] * ss[q];
            ks1[q] += e1[q];
            ks2[q] += e2[q];
        }
        float4 v1 = *(const float4*)(kp + 1024 + jc);
        float4 v2 = *(const float4*)(kp + 1024 + jc + 32);
        *(float4*)&Vsm[lrow][jc]      = v1;
        *(float4*)&Vsm[lrow][jc + 32] = v2;
        __syncthreads();
#pragma unroll 8
        for (int k = 0; k < 32; k++) {
            float4 a4 = *(const float4*)&Ksm[k][ti * 4];
            float4 b4 = *(const float4*)&Vsm[k][td * 4];
            float a[4] = {a4.x, a4.y, a4.z, a4.w};
            float bb[4] = {b4.x, b4.y, b4.z, b4.w};
#pragma unroll
            for (int i = 0; i < 4; i++)
#pragma unroll
                for (int j = 0; j < 4; j++) acc[i][j] += a[i] * bb[j];
        }
        __syncthreads();
    }

#pragma unroll
    for (int q = 0; q < 4; q++) {
        red[lrow][jc + q]      = ks1[q];
        red[lrow][jc + 32 + q] = ks2[q];
    }
    __syncthreads();
    if (tid < 64) {
        float s = 0.0f;
#pragma unroll
        for (int r = 0; r < 32; r++) s += red[r][tid];
        g_Kpart[split][bh * 64 + tid] = s;
    }

    float* mp = &g_Mpart[split][bh * 4096];
#pragma unroll
    for (int i = 0; i < 4; i++) {
        float4 o = make_float4(acc[i][0], acc[i][1], acc[i][2], acc[i][3]);
        *(float4*)&mp[(ti * 4 + i) * 64 + td * 4] = o;
    }
}

// ---------------- reduce split-K partials (deterministic) ----------------
__global__ void reduce_parts_kernel() {
    int idx = blockIdx.x * 256 + threadIdx.x;
    if (idx < BHc * 4096) {
        float s = 0.0f;
#pragma unroll
        for (int sp = 0; sp < NSPLIT; sp++) s += g_Mpart[sp][idx];
        g_M[idx] = s;
    } else if (idx < BHc * 4096 + BHc * 64) {
        int i2 = idx - BHc * 4096;
        float s = 0.0f;
#pragma unroll
        for (int sp = 0; sp < NSPLIT; sp++) s += g_Kpart[sp][i2];
        g_Ksum[i2] = s;
    }
}

// ---------------- y = (rope(elu(Q)+1) @ M) / (elu(Q)+1 . Ksum) -> fp16 ----------------
__global__ __launch_bounds__(256)
void compute_y_kernel() {
    const int bh = blockIdx.x, tchunk = blockIdx.y;
    const int b = bh >> 4, h = bh & 15;
    const int t0 = tchunk * 64;
    __shared__ float smA[64 * 65];
    __shared__ float qrot[64 * 65];
    __shared__ float ks[64];
    __shared__ float den[64];
    const int tid = threadIdx.x;

    if (tid < 64) ks[tid] = g_Ksum[bh * 64 + tid];

#pragma unroll
    for (int it = 0; it < 4; it++) {
        int idx = tid + it * 256;
        int r = idx >> 4, c4 = (idx & 15) * 4;
        float4 qv = *(const float4*)&g_Q[(size_t)(b * Tc + t0 + r) * 1024 + h * 64 + c4];
        smA[r * 65 + c4 + 0] = eluplus(qv.x);
        smA[r * 65 + c4 + 1] = eluplus(qv.y);
        smA[r * 65 + c4 + 2] = eluplus(qv.z);
        smA[r * 65 + c4 + 3] = eluplus(qv.w);
    }
    __syncthreads();

#pragma unroll
    for (int it = 0; it < 8; it++) {
        int idx = tid + it * 256;
        int r = idx >> 5, j = idx & 31;
        float e1 = smA[r * 65 + j], e2 = smA[r * 65 + j + 32];
        int t = t0 + r;
        float c = g_cos[t * 32 + j], si = g_sin[t * 32 + j];
        qrot[r * 65 + j]      = e1 * c - e2 * si;
        qrot[r * 65 + j + 32] = e2 * c + e1 * si;
    }
    if (tid < 64) {
        float s = 0.0f;
#pragma unroll
        for (int d = 0; d < 64; d++) s += smA[tid * 65 + d] * ks[d];
        den[tid] = s;
    }
    __syncthreads();

#pragma unroll
    for (int it = 0; it < 16; it++) {
        int idx = tid + it * 256;
        smA[idx] = g_M[bh * 4096 + idx];
    }
    __syncthreads();

    const int row = tid >> 2;
    const int dg = (tid & 3) * 16;
    float acc[16];
#pragma unroll
    for (int i = 0; i < 16; i++) acc[i] = 0.0f;
#pragma unroll
    for (int k = 0; k < 64; k++) {
        float qv = qrot[row * 65 + k];
#pragma unroll
        for (int q = 0; q < 4; q++) {
            float4 mv = *(const float4*)&smA[k * 64 + dg + q * 4];
            acc[q * 4 + 0] += qv * mv.x;
            acc[q * 4 + 1] += qv * mv.y;
            acc[q * 4 + 2] += qv * mv.z;
            acc[q * 4 + 3] += qv * mv.w;
        }
    }
    float inv = 1.0f / den[row];
    size_t yoff = (size_t)(b * Tc + t0 + row) * 1024 + h * 64 + dg;
    __half hv[16];
#pragma unroll
    for (int i = 0; i < 16; i++) hv[i] = __float2half_rn(acc[i] * inv);
    *(uint4*)(g_yh + yoff)     = *(uint4*)hv;
    *(uint4*)(g_yh + yoff + 8) = *(uint4*)(hv + 8);
}

// ---------------- launch ----------------
extern "C" void kernel_launch(void* const* d_in, const int* in_sizes, int n_in,
                              void* d_out, int out_size) {
    const float* x      = (const float*)d_in[0];
    const float* memory = (const float*)d_in[1];
    const float* q_w    = (const float*)d_in[2];
    const float* q_b    = (const float*)d_in[3];
    const float* kv_w   = (const float*)d_in[4];
    const float* kv_b   = (const float*)d_in[5];
    const float* proj_w = (const float*)d_in[6];
    const float* proj_b = (const float*)d_in[7];
    float* out = (float*)d_out;

    cudaFuncSetAttribute(tc_gemm, cudaFuncAttributeMaxDynamicSharedMemorySize, SM_TOTAL);

    float *pQ, *pKV;
    cudaGetSymbolAddress((void**)&pQ,  g_Q);
    cudaGetSymbolAddress((void**)&pKV, g_KV);
    __half *xh, *mh, *yh, *kwh, *kwl, *qwh, *qwl, *pwh, *pwl;
    cudaGetSymbolAddress((void**)&xh, g_xh);
    cudaGetSymbolAddress((void**)&mh, g_mh);
    cudaGetSymbolAddress((void**)&yh, g_yh);
    cudaGetSymbolAddress((void**)&kwh, g_kvwt_hi); cudaGetSymbolAddress((void**)&kwl, g_kvwt_lo);
    cudaGetSymbolAddress((void**)&qwh, g_qwt_hi);  cudaGetSymbolAddress((void**)&qwl, g_qwt_lo);
    cudaGetSymbolAddress((void**)&pwh, g_pwt_hi);  cudaGetSymbolAddress((void**)&pwl, g_pwt_lo);

    rope_table_kernel<<<(Sc * 32 + 255) / 256, 256>>>();

    // operand prep
    wtrans_split_kernel<<<dim3(2 * Cc / 32, Cc / 32), dim3(32, 8)>>>(kv_w, kwh, kwl, Cc, 2 * Cc);
    wtrans_split_kernel<<<dim3(Cc / 32, Cc / 32), dim3(32, 8)>>>(q_w, qwh, qwl, Cc, Cc);
    wtrans_split_kernel<<<dim3(Cc / 32, Cc / 32), dim3(32, 8)>>>(proj_w, pwh, pwl, Cc, Cc);
    act_f16_kernel<<<(Bc * Sc * Cc / 4 + 255) / 256, 256>>>(memory, mh, Bc * Sc * Cc / 4);
    act_f16_kernel<<<(Bc * Tc * Cc / 4 + 255) / 256, 256>>>(x, xh, Bc * Tc * Cc / 4);

    // KV = memory @ kv_w + kv_b
    tc_gemm<<<dim3(2 * Cc / GBN, Bc * Sc / GBM), 256, SM_TOTAL>>>(mh, kwh, kwl, kv_b, pKV, 2 * Cc);
    // Q = x @ q_w + q_b
    tc_gemm<<<dim3(Cc / GBN, Bc * Tc / GBM), 256, SM_TOTAL>>>(xh, qwh, qwl, q_b, pQ, Cc);

    // fused elu+rope+Ksum + M partials
    compute_mpart_kernel<<<dim3(BHc, NSPLIT), 256>>>();
    reduce_parts_kernel<<<(BHc * 4096 + BHc * 64 + 255) / 256, 256>>>();
    compute_y_kernel<<<dim3(BHc, Tc / 64), 256>>>();

    // out = Y @ proj_w + proj_b
    tc_gemm<<<dim3(Cc / GBN, Bc * Tc / GBM), 256, SM_TOTAL>>>(yh, pwh, pwl, proj_b, out, Cc);
}

// round 16
// speedup vs baseline: 1.4854x; 1.4854x over previous
#include <cuda_runtime.h>
#include <cuda_fp16.h>
#include <cstdint>
#include <math.h>

// Shapes (fixed by the problem)
#define Bc 2
#define Tc 2048
#define Sc 2048
#define Cc 1024
#define Hc 16
#define HDc 64
#define BHc (Bc*Hc)          // 32
#define NSPLIT 16

// ---------------- scratch (device globals; no allocation allowed) ----------------
__device__ float g_Q [Bc*Tc*Cc];                 // Q projection (fp32)
__device__ float g_KV[Bc*Sc*2*Cc];               // KV projection (fp32, raw)
__device__ float g_cos[Sc*32];
__device__ float g_sin[Sc*32];
__device__ float g_Kpart[NSPLIT][BHc*HDc];
__device__ float g_Ksum [BHc*HDc];
__device__ float g_Mpart[NSPLIT][BHc*HDc*HDc];
__device__ float g_M    [BHc*HDc*HDc];

// fp16 operands (K-major, K = 1024). Activations single; weights hi/lo split.
__device__ __half g_xh[Bc*Tc*Cc];                  // x (single fp16)
__device__ __half g_mh[Bc*Sc*Cc];                  // memory
__device__ __half g_yh[Bc*Tc*Cc];                  // attention out
__device__ __half g_kvwt_hi[2*Cc*Cc], g_kvwt_lo[2*Cc*Cc];  // kv_w^T [2048,1024]
__device__ __half g_qwt_hi [Cc*Cc],   g_qwt_lo [Cc*Cc];    // q_w^T
__device__ __half g_pwt_hi [Cc*Cc],   g_pwt_lo [Cc*Cc];    // proj_w^T

__device__ __forceinline__ float eluplus(float x) {
    return x > 0.0f ? x + 1.0f : expf(x);
}

// ================= mma.sync helpers (sm_80 baseline; safe on compute_103) =================
__device__ __forceinline__ uint32_t smem_u32(const void* p) {
    uint32_t a;
    asm("{ .reg .u64 t; cvta.to.shared.u64 t, %1; cvt.u32.u64 %0, t; }" : "=r"(a) : "l"(p));
    return a;
}
__device__ __forceinline__ void cpa16(uint32_t dst, const void* src) {
    asm volatile("cp.async.cg.shared.global [%0], [%1], 16;" :: "r"(dst), "l"(src));
}
__device__ __forceinline__ void ldsm_x4(uint32_t* r, uint32_t addr) {
    asm volatile("ldmatrix.sync.aligned.m8n8.x4.shared.b16 {%0,%1,%2,%3}, [%4];"
        : "=r"(r[0]), "=r"(r[1]), "=r"(r[2]), "=r"(r[3]) : "r"(addr));
}
__device__ __forceinline__ void mma16816h(float* c, const uint32_t* a, const uint32_t* b) {
    asm volatile("mma.sync.aligned.m16n8k16.row.col.f32.f16.f16.f32 "
        "{%0,%1,%2,%3}, {%4,%5,%6,%7}, {%8,%9}, {%0,%1,%2,%3};"
        : "+f"(c[0]), "+f"(c[1]), "+f"(c[2]), "+f"(c[3])
        : "r"(a[0]), "r"(a[1]), "r"(a[2]), "r"(a[3]), "r"(b[0]), "r"(b[1]));
}

// ================= fp16x2 HMMA GEMM: C[M,N] = A[M,K] @ (Wh+Wl)[N,K]^T + bias =================
// Tile 256x128 (MxN), BK=32, K=1024 fixed, 4-stage cp.async pipeline. (R12 optimum)
#define GBM 256
#define GBN 128
#define GBK 32
#define GK  1024
#define GNIT (GK / GBK)            // 32
#define ROWB 80                    // bytes per smem row (32 fp16 + 8 pad)
#define A_BYTES (256 * ROWB)       // 20480
#define B_BYTES (128 * ROWB)       // 10240
#define OFF_A  0
#define OFF_BH (A_BYTES)
#define OFF_BL (A_BYTES + B_BYTES)
#define STAGE_BYTES (A_BYTES + 2 * B_BYTES)   // 40960
#define NSTAGE 4
#define SM_TOTAL (NSTAGE * STAGE_BYTES)       // 163840

__global__ __launch_bounds__(256, 1)
void tc_gemm(const __half* __restrict__ A,
             const __half* __restrict__ Bh, const __half* __restrict__ Bl,
             const float* __restrict__ bias, float* __restrict__ C, int N) {
    extern __shared__ char smem[];
    const uint32_t sb = smem_u32(smem);
    const int tid = threadIdx.x, wid = tid >> 5, lane = tid & 31;
    const int wm = wid >> 1, wn = wid & 1;             // 4 x 2 warp grid
    const int m0 = blockIdx.y * GBM, n0 = blockIdx.x * GBN;

    float acc[4][8][4];
#pragma unroll
    for (int i = 0; i < 4; i++)
#pragma unroll
        for (int j = 0; j < 8; j++)
#pragma unroll
            for (int q = 0; q < 4; q++) acc[i][j][q] = 0.0f;

    // loader mapping: 16B chunks. A: 1024 chunks (4/thread); Bh,Bl: 512 each (2/thread)
    const int lrow = tid >> 2;             // 0..63
    const int lcol = (tid & 3) * 8;        // fp16 col offset (0,8,16,24)
    const uint32_t ldst = (uint32_t)(lrow * ROWB + lcol * 2);

    auto prefetch = [&](int it) {
        const int st = it & (NSTAGE - 1);
        const int k0 = it * GBK;
        const uint32_t base = sb + st * STAGE_BYTES;
#pragma unroll
        for (int p = 0; p < 4; p++) {
            const size_t asrc = (size_t)(m0 + lrow + 64 * p) * GK + k0 + lcol;
            cpa16(base + OFF_A + ldst + (uint32_t)(p * 64 * ROWB), A + asrc);
        }
#pragma unroll
        for (int p = 0; p < 2; p++) {
            const size_t bsrc = (size_t)(n0 + lrow + 64 * p) * GK + k0 + lcol;
            cpa16(base + OFF_BH + ldst + (uint32_t)(p * 64 * ROWB), Bh + bsrc);
            cpa16(base + OFF_BL + ldst + (uint32_t)(p * 64 * ROWB), Bl + bsrc);
        }
        asm volatile("cp.async.commit_group;" ::: "memory");
    };

    prefetch(0); prefetch(1); prefetch(2);

    // fragment smem addresses (relative to stage base)
    const uint32_t a_rb = (uint32_t)((wm * 64 + (lane & 15)) * ROWB + (lane >> 4) * 16);
    const uint32_t b_rb = (uint32_t)((wn * 64 + (lane & 15)) * ROWB + (lane >> 4) * 16);

    for (int it = 0; it < GNIT; it++) {
        if (it + 3 < GNIT)      { asm volatile("cp.async.wait_group 2;" ::: "memory"); }
        else if (it + 2 < GNIT) { asm volatile("cp.async.wait_group 1;" ::: "memory"); }
        else                    { asm volatile("cp.async.wait_group 0;" ::: "memory"); }
        __syncthreads();
        if (it + 3 < GNIT) prefetch(it + 3);

        const uint32_t base = sb + (it & (NSTAGE - 1)) * STAGE_BYTES;
#pragma unroll
        for (int kk = 0; kk < 2; kk++) {               // two k16 steps per BK=32
            const uint32_t koff = (uint32_t)(kk * 32);  // 16 fp16 = 32 bytes
            // B fragments: pair p covers nf(2p), nf(2p+1) in regs {r[o], r[o+2]}
            uint32_t bhf[4][4], blf[4][4];
#pragma unroll
            for (int p = 0; p < 4; p++) {
                uint32_t bd = base + b_rb + (uint32_t)(p * 16 * ROWB) + koff;
                ldsm_x4(bhf[p], bd + OFF_BH);
                ldsm_x4(blf[p], bd + OFF_BL);
            }
#pragma unroll
            for (int mf = 0; mf < 4; mf++) {
                uint32_t ad = base + a_rb + (uint32_t)(mf * 16 * ROWB) + koff;
                uint32_t af[4];
                ldsm_x4(af, ad + OFF_A);
#pragma unroll
                for (int nf = 0; nf < 8; nf++) {
                    const int p = nf >> 1, o = nf & 1;
                    uint32_t bhv[2] = {bhf[p][o], bhf[p][o + 2]};
                    uint32_t blv[2] = {blf[p][o], blf[p][o + 2]};
                    mma16816h(acc[mf][nf], af, bhv);
                    mma16816h(acc[mf][nf], af, blv);
                }
            }
        }
    }

    // epilogue: direct stores with bias
#pragma unroll
    for (int mf = 0; mf < 4; mf++) {
        const int r0 = m0 + wm * 64 + mf * 16 + (lane >> 2);
#pragma unroll
        for (int nf = 0; nf < 8; nf++) {
            const int col = n0 + wn * 64 + nf * 8 + (lane & 3) * 2;
            const float b0 = bias[col], b1 = bias[col + 1];
            float* p0 = C + (size_t)r0 * N + col;
            float2 v0 = make_float2(acc[mf][nf][0] + b0, acc[mf][nf][1] + b1);
            float2 v1 = make_float2(acc[mf][nf][2] + b0, acc[mf][nf][3] + b1);
            *(float2*)p0 = v0;
            *(float2*)(p0 + 8 * N) = v1;
        }
    }
}

// ---------------- operand preparation ----------------
// activations: fp32 -> single fp16
__global__ void act_f16_kernel(const float* __restrict__ A,
                               __half* __restrict__ H, int n4) {
    int i = blockIdx.x * 256 + threadIdx.x;
    if (i >= n4) return;
    float4 v = *(const float4*)(A + (size_t)i * 4);
    __half h[4] = {__float2half_rn(v.x), __float2half_rn(v.y),
                   __float2half_rn(v.z), __float2half_rn(v.w)};
    *(uint2*)(H + (size_t)i * 4) = *(uint2*)h;
}

// weights: transpose + fp16 hi/lo split: W[K,N] -> Wt_hi/lo[N,K]
__global__ void wtrans_split_kernel(const float* __restrict__ W,
                                    __half* __restrict__ th,
                                    __half* __restrict__ tl, int K, int N) {
    __shared__ float t[32][33];
    int k0 = blockIdx.y * 32, n0 = blockIdx.x * 32;
    int tx = threadIdx.x, ty = threadIdx.y;
#pragma unroll
    for (int i = ty; i < 32; i += 8)
        t[i][tx] = W[(size_t)(k0 + i) * N + n0 + tx];
    __syncthreads();
#pragma unroll
    for (int i = ty; i < 32; i += 8) {
        float v = t[tx][i];
        __half h = __float2half_rn(v);
        size_t o = (size_t)(n0 + i) * K + k0 + tx;
        th[o] = h;
        tl[o] = __float2half_rn(v - __half2float(h));
    }
}

// ---------------- rope cos/sin table ----------------
__global__ void rope_table_kernel() {
    int idx = blockIdx.x * blockDim.x + threadIdx.x;
    if (idx >= Sc * 32) return;
    int t = idx >> 5, j = idx & 31;
    float ex = (float)(2 * j) / 64.0f;
    float invf = 1.0f / powf(10000.0f, ex);
    float ang = (float)t * invf;
    float s, c;
    sincosf(ang, &s, &c);
    g_cos[idx] = c;
    g_sin[idx] = s;
}

// ---------------- fused: elu+rope K on the fly, Mpart = K_rot^T V, Ksum partials ----------------
__global__ __launch_bounds__(256)
void compute_mpart_kernel() {
    const int bh = blockIdx.x, split = blockIdx.y;
    const int b = bh >> 4, h = bh & 15;
    __shared__ float Ksm[32][64];
    __shared__ float Vsm[32][68];
    __shared__ float red[32][64];
    const int tid = threadIdx.x;
    const int ti = tid >> 4, td = tid & 15;
    const int lrow = tid >> 3;                  // 0..31
    const int jc = (tid & 7) * 4;               // pair-col base 0..28

    float acc[4][4];
#pragma unroll
    for (int i = 0; i < 4; i++)
#pragma unroll
        for (int j = 0; j < 4; j++) acc[i][j] = 0.0f;
    float ks1[4] = {0, 0, 0, 0}, ks2[4] = {0, 0, 0, 0};

    for (int kt = 0; kt < 4; kt++) {
        const int s = split * 128 + kt * 32 + lrow;
        const float* kp = &g_KV[(size_t)(b * Sc + s) * 2048 + h * 64];
        float4 k1 = *(const float4*)(kp + jc);
        float4 k2 = *(const float4*)(kp + jc + 32);
        float4 c4 = *(const float4*)&g_cos[s * 32 + jc];
        float4 s4 = *(const float4*)&g_sin[s * 32 + jc];
        float e1[4] = {eluplus(k1.x), eluplus(k1.y), eluplus(k1.z), eluplus(k1.w)};
        float e2[4] = {eluplus(k2.x), eluplus(k2.y), eluplus(k2.z), eluplus(k2.w)};
        float cc[4] = {c4.x, c4.y, c4.z, c4.w};
        float ss[4] = {s4.x, s4.y, s4.z, s4.w};
#pragma unroll
        for (int q = 0; q < 4; q++) {
            Ksm[lrow][jc + q]      = e1[q] * cc[q] - e2[q] * ss[q];
            Ksm[lrow][jc + 32 + q] = e2[q] * cc[q] + e1[q] * ss[q];
            ks1[q] += e1[q];
            ks2[q] += e2[q];
        }
        float4 v1 = *(const float4*)(kp + 1024 + jc);
        float4 v2 = *(const float4*)(kp + 1024 + jc + 32);
        *(float4*)&Vsm[lrow][jc]      = v1;
        *(float4*)&Vsm[lrow][jc + 32] = v2;
        __syncthreads();
#pragma unroll 8
        for (int k = 0; k < 32; k++) {
            float4 a4 = *(const float4*)&Ksm[k][ti * 4];
            float4 b4 = *(const float4*)&Vsm[k][td * 4];
            float a[4] = {a4.x, a4.y, a4.z, a4.w};
            float bb[4] = {b4.x, b4.y, b4.z, b4.w};
#pragma unroll
            for (int i = 0; i < 4; i++)
#pragma unroll
                for (int j = 0; j < 4; j++) acc[i][j] += a[i] * bb[j];
        }
        __syncthreads();
    }

#pragma unroll
    for (int q = 0; q < 4; q++) {
        red[lrow][jc + q]      = ks1[q];
        red[lrow][jc + 32 + q] = ks2[q];
    }
    __syncthreads();
    if (tid < 64) {
        float s = 0.0f;
#pragma unroll
        for (int r = 0; r < 32; r++) s += red[r][tid];
        g_Kpart[split][bh * 64 + tid] = s;
    }

    float* mp = &g_Mpart[split][bh * 4096];
#pragma unroll
    for (int i = 0; i < 4; i++) {
        float4 o = make_float4(acc[i][0], acc[i][1], acc[i][2], acc[i][3]);
        *(float4*)&mp[(ti * 4 + i) * 64 + td * 4] = o;
    }
}

// ---------------- reduce split-K partials (deterministic) ----------------
__global__ void reduce_parts_kernel() {
    int idx = blockIdx.x * 256 + threadIdx.x;
    if (idx < BHc * 4096) {
        float s = 0.0f;
#pragma unroll
        for (int sp = 0; sp < NSPLIT; sp++) s += g_Mpart[sp][idx];
        g_M[idx] = s;
    } else if (idx < BHc * 4096 + BHc * 64) {
        int i2 = idx - BHc * 4096;
        float s = 0.0f;
#pragma unroll
        for (int sp = 0; sp < NSPLIT; sp++) s += g_Kpart[sp][i2];
        g_Ksum[i2] = s;
    }
}

// ---------------- y = (rope(elu(Q)+1) @ M) / (elu(Q)+1 . Ksum) -> fp16 ----------------
__global__ __launch_bounds__(256)
void compute_y_kernel() {
    const int bh = blockIdx.x, tchunk = blockIdx.y;
    const int b = bh >> 4, h = bh & 15;
    const int t0 = tchunk * 64;
    __shared__ float smA[64 * 65];
    __shared__ float qrot[64 * 65];
    __shared__ float ks[64];
    __shared__ float den[64];
    const int tid = threadIdx.x;

    if (tid < 64) ks[tid] = g_Ksum[bh * 64 + tid];

#pragma unroll
    for (int it = 0; it < 4; it++) {
        int idx = tid + it * 256;
        int r = idx >> 4, c4 = (idx & 15) * 4;
        float4 qv = *(const float4*)&g_Q[(size_t)(b * Tc + t0 + r) * 1024 + h * 64 + c4];
        smA[r * 65 + c4 + 0] = eluplus(qv.x);
        smA[r * 65 + c4 + 1] = eluplus(qv.y);
        smA[r * 65 + c4 + 2] = eluplus(qv.z);
        smA[r * 65 + c4 + 3] = eluplus(qv.w);
    }
    __syncthreads();

#pragma unroll
    for (int it = 0; it < 8; it++) {
        int idx = tid + it * 256;
        int r = idx >> 5, j = idx & 31;
        float e1 = smA[r * 65 + j], e2 = smA[r * 65 + j + 32];
        int t = t0 + r;
        float c = g_cos[t * 32 + j], si = g_sin[t * 32 + j];
        qrot[r * 65 + j]      = e1 * c - e2 * si;
        qrot[r * 65 + j + 32] = e2 * c + e1 * si;
    }
    if (tid < 64) {
        float s = 0.0f;
#pragma unroll
        for (int d = 0; d < 64; d++) s += smA[tid * 65 + d] * ks[d];
        den[tid] = s;
    }
    __syncthreads();

#pragma unroll
    for (int it = 0; it < 16; it++) {
        int idx = tid + it * 256;
        smA[idx] = g_M[bh * 4096 + idx];
    }
    __syncthreads();

    const int row = tid >> 2;
    const int dg = (tid & 3) * 16;
    float acc[16];
#pragma unroll
    for (int i = 0; i < 16; i++) acc[i] = 0.0f;
#pragma unroll
    for (int k = 0; k < 64; k++) {
        float qv = qrot[row * 65 + k];
#pragma unroll
        for (int q = 0; q < 4; q++) {
            float4 mv = *(const float4*)&smA[k * 64 + dg + q * 4];
            acc[q * 4 + 0] += qv * mv.x;
            acc[q * 4 + 1] += qv * mv.y;
            acc[q * 4 + 2] += qv * mv.z;
            acc[q * 4 + 3] += qv * mv.w;
        }
    }
    float inv = 1.0f / den[row];
    size_t yoff = (size_t)(b * Tc + t0 + row) * 1024 + h * 64 + dg;
    __half hv[16];
#pragma unroll
    for (int i = 0; i < 16; i++) hv[i] = __float2half_rn(acc[i] * inv);
    *(uint4*)(g_yh + yoff)     = *(uint4*)hv;
    *(uint4*)(g_yh + yoff + 8) = *(uint4*)(hv + 8);
}

// ---------------- launch (multi-stream fork/join inside the captured graph) ----------------
extern "C" void kernel_launch(void* const* d_in, const int* in_sizes, int n_in,
                              void* d_out, int out_size) {
    const float* x      = (const float*)d_in[0];
    const float* memory = (const float*)d_in[1];
    const float* q_w    = (const float*)d_in[2];
    const float* q_b    = (const float*)d_in[3];
    const float* kv_w   = (const float*)d_in[4];
    const float* kv_b   = (const float*)d_in[5];
    const float* proj_w = (const float*)d_in[6];
    const float* proj_b = (const float*)d_in[7];
    float* out = (float*)d_out;

    cudaFuncSetAttribute(tc_gemm, cudaFuncAttributeMaxDynamicSharedMemorySize, SM_TOTAL);

    float *pQ, *pKV;
    cudaGetSymbolAddress((void**)&pQ,  g_Q);
    cudaGetSymbolAddress((void**)&pKV, g_KV);
    __half *xh, *mh, *yh, *kwh, *kwl, *qwh, *qwl, *pwh, *pwl;
    cudaGetSymbolAddress((void**)&xh, g_xh);
    cudaGetSymbolAddress((void**)&mh, g_mh);
    cudaGetSymbolAddress((void**)&yh, g_yh);
    cudaGetSymbolAddress((void**)&kwh, g_kvwt_hi); cudaGetSymbolAddress((void**)&kwl, g_kvwt_lo);
    cudaGetSymbolAddress((void**)&qwh, g_qwt_hi);  cudaGetSymbolAddress((void**)&qwl, g_qwt_lo);
    cudaGetSymbolAddress((void**)&pwh, g_pwt_hi);  cudaGetSymbolAddress((void**)&pwl, g_pwt_lo);

    // one-time host-side infra (stream/event handles; no device memory involved)
    static cudaStream_t s_q = nullptr, s_w = nullptr;
    static cudaEvent_t ev_root = nullptr, ev_q = nullptr, ev_w = nullptr;
    if (s_q == nullptr) {
        cudaStreamCreateWithFlags(&s_q, cudaStreamNonBlocking);
        cudaStreamCreateWithFlags(&s_w, cudaStreamNonBlocking);
        cudaEventCreateWithFlags(&ev_root, cudaEventDisableTiming);
        cudaEventCreateWithFlags(&ev_q,    cudaEventDisableTiming);
        cudaEventCreateWithFlags(&ev_w,    cudaEventDisableTiming);
    }

    // fork side streams off the origin stream
    cudaEventRecord(ev_root, 0);
    cudaStreamWaitEvent(s_q, ev_root, 0);
    cudaStreamWaitEvent(s_w, ev_root, 0);

    // ---- side stream s_q: Q path (independent of KV path) ----
    wtrans_split_kernel<<<dim3(Cc / 32, Cc / 32), dim3(32, 8), 0, s_q>>>(q_w, qwh, qwl, Cc, Cc);
    act_f16_kernel<<<(Bc * Tc * Cc / 4 + 255) / 256, 256, 0, s_q>>>(x, xh, Bc * Tc * Cc / 4);
    tc_gemm<<<dim3(Cc / GBN, Bc * Tc / GBM), 256, SM_TOTAL, s_q>>>(xh, qwh, qwl, q_b, pQ, Cc);
    cudaEventRecord(ev_q, s_q);

    // ---- side stream s_w: proj weight prep (needed only by final GEMM) ----
    wtrans_split_kernel<<<dim3(Cc / 32, Cc / 32), dim3(32, 8), 0, s_w>>>(proj_w, pwh, pwl, Cc, Cc);
    cudaEventRecord(ev_w, s_w);

    // ---- origin stream: KV path (critical chain) ----
    rope_table_kernel<<<(Sc * 32 + 255) / 256, 256>>>();
    act_f16_kernel<<<(Bc * Sc * Cc / 4 + 255) / 256, 256>>>(memory, mh, Bc * Sc * Cc / 4);
    wtrans_split_kernel<<<dim3(2 * Cc / 32, Cc / 32), dim3(32, 8)>>>(kv_w, kwh, kwl, Cc, 2 * Cc);
    tc_gemm<<<dim3(2 * Cc / GBN, Bc * Sc / GBM), 256, SM_TOTAL>>>(mh, kwh, kwl, kv_b, pKV, 2 * Cc);
    compute_mpart_kernel<<<dim3(BHc, NSPLIT), 256>>>();
    reduce_parts_kernel<<<(BHc * 4096 + BHc * 64 + 255) / 256, 256>>>();

    // join: compute_y needs Q (s_q); final GEMM needs proj weights (s_w)
    cudaStreamWaitEvent(0, ev_q, 0);
    compute_y_kernel<<<dim3(BHc, Tc / 64), 256>>>();
    cudaStreamWaitEvent(0, ev_w, 0);
    tc_gemm<<<dim3(Cc / GBN, Bc * Tc / GBM), 256, SM_TOTAL>>>(yh, pwh, pwl, proj_b, out, Cc);
}

// round 17
// speedup vs baseline: 1.5183x; 1.0222x over previous
#include <cuda_runtime.h>
#include <cuda_fp16.h>
#include <cstdint>
#include <math.h>

// Shapes (fixed by the problem)
#define Bc 2
#define Tc 2048
#define Sc 2048
#define Cc 1024
#define Hc 16
#define HDc 64
#define BHc (Bc*Hc)          // 32
#define NSPLIT 16

// ---------------- scratch (device globals; no allocation allowed) ----------------
__device__ float g_Q [Bc*Tc*Cc];                 // Q projection (fp32)
__device__ float g_KV[Bc*Sc*2*Cc];               // KV projection (fp32, raw)
__device__ float g_cos[Sc*32];
__device__ float g_sin[Sc*32];
__device__ float g_Kpart[NSPLIT][BHc*HDc];
__device__ float g_Ksum [BHc*HDc];
__device__ float g_Mpart[NSPLIT][BHc*HDc*HDc];
__device__ float g_M    [BHc*HDc*HDc];

// fp16 operands (K-major, K = 1024). Activations single; weights hi/lo split.
__device__ __half g_xh[Bc*Tc*Cc];                  // x (single fp16)
__device__ __half g_mh[Bc*Sc*Cc];                  // memory
__device__ __half g_yh[Bc*Tc*Cc];                  // attention out
__device__ __half g_kvwt_hi[2*Cc*Cc], g_kvwt_lo[2*Cc*Cc];  // kv_w^T [2048,1024]
__device__ __half g_qwt_hi [Cc*Cc],   g_qwt_lo [Cc*Cc];    // q_w^T
__device__ __half g_pwt_hi [Cc*Cc],   g_pwt_lo [Cc*Cc];    // proj_w^T

__device__ __forceinline__ float eluplus(float x) {
    return x > 0.0f ? x + 1.0f : expf(x);
}

// ================= mma.sync helpers (sm_80 baseline; safe on compute_103) =================
__device__ __forceinline__ uint32_t smem_u32(const void* p) {
    uint32_t a;
    asm("{ .reg .u64 t; cvta.to.shared.u64 t, %1; cvt.u32.u64 %0, t; }" : "=r"(a) : "l"(p));
    return a;
}
__device__ __forceinline__ void cpa16(uint32_t dst, const void* src) {
    asm volatile("cp.async.cg.shared.global [%0], [%1], 16;" :: "r"(dst), "l"(src));
}
__device__ __forceinline__ void ldsm_x4(uint32_t* r, uint32_t addr) {
    asm volatile("ldmatrix.sync.aligned.m8n8.x4.shared.b16 {%0,%1,%2,%3}, [%4];"
        : "=r"(r[0]), "=r"(r[1]), "=r"(r[2]), "=r"(r[3]) : "r"(addr));
}
__device__ __forceinline__ void mma16816h(float* c, const uint32_t* a, const uint32_t* b) {
    asm volatile("mma.sync.aligned.m16n8k16.row.col.f32.f16.f16.f32 "
        "{%0,%1,%2,%3}, {%4,%5,%6,%7}, {%8,%9}, {%0,%1,%2,%3};"
        : "+f"(c[0]), "+f"(c[1]), "+f"(c[2]), "+f"(c[3])
        : "r"(a[0]), "r"(a[1]), "r"(a[2]), "r"(a[3]), "r"(b[0]), "r"(b[1]));
}

// ================= fp16x2 HMMA GEMM: C[M,N] = A[M,K] @ (Wh+Wl)[N,K]^T + bias =================
// Tile 256x128 (MxN), BK=32, K=1024 fixed, 4-stage cp.async pipeline. (R12 optimum)
#define GBM 256
#define GBN 128
#define GBK 32
#define GK  1024
#define GNIT (GK / GBK)            // 32
#define ROWB 80                    // bytes per smem row (32 fp16 + 8 pad)
#define A_BYTES (256 * ROWB)       // 20480
#define B_BYTES (128 * ROWB)       // 10240
#define OFF_A  0
#define OFF_BH (A_BYTES)
#define OFF_BL (A_BYTES + B_BYTES)
#define STAGE_BYTES (A_BYTES + 2 * B_BYTES)   // 40960
#define NSTAGE 4
#define SM_TOTAL (NSTAGE * STAGE_BYTES)       // 163840

__global__ __launch_bounds__(256, 1)
void tc_gemm(const __half* __restrict__ A,
             const __half* __restrict__ Bh, const __half* __restrict__ Bl,
             const float* __restrict__ bias, float* __restrict__ C, int N) {
    extern __shared__ char smem[];
    const uint32_t sb = smem_u32(smem);
    const int tid = threadIdx.x, wid = tid >> 5, lane = tid & 31;
    const int wm = wid >> 1, wn = wid & 1;             // 4 x 2 warp grid
    const int m0 = blockIdx.y * GBM, n0 = blockIdx.x * GBN;

    float acc[4][8][4];
#pragma unroll
    for (int i = 0; i < 4; i++)
#pragma unroll
        for (int j = 0; j < 8; j++)
#pragma unroll
            for (int q = 0; q < 4; q++) acc[i][j][q] = 0.0f;

    // loader mapping: 16B chunks. A: 1024 chunks (4/thread); Bh,Bl: 512 each (2/thread)
    const int lrow = tid >> 2;             // 0..63
    const int lcol = (tid & 3) * 8;        // fp16 col offset (0,8,16,24)
    const uint32_t ldst = (uint32_t)(lrow * ROWB + lcol * 2);

    auto prefetch = [&](int it) {
        const int st = it & (NSTAGE - 1);
        const int k0 = it * GBK;
        const uint32_t base = sb + st * STAGE_BYTES;
#pragma unroll
        for (int p = 0; p < 4; p++) {
            const size_t asrc = (size_t)(m0 + lrow + 64 * p) * GK + k0 + lcol;
            cpa16(base + OFF_A + ldst + (uint32_t)(p * 64 * ROWB), A + asrc);
        }
#pragma unroll
        for (int p = 0; p < 2; p++) {
            const size_t bsrc = (size_t)(n0 + lrow + 64 * p) * GK + k0 + lcol;
            cpa16(base + OFF_BH + ldst + (uint32_t)(p * 64 * ROWB), Bh + bsrc);
            cpa16(base + OFF_BL + ldst + (uint32_t)(p * 64 * ROWB), Bl + bsrc);
        }
        asm volatile("cp.async.commit_group;" ::: "memory");
    };

    prefetch(0); prefetch(1); prefetch(2);

    // fragment smem addresses (relative to stage base)
    const uint32_t a_rb = (uint32_t)((wm * 64 + (lane & 15)) * ROWB + (lane >> 4) * 16);
    const uint32_t b_rb = (uint32_t)((wn * 64 + (lane & 15)) * ROWB + (lane >> 4) * 16);

    for (int it = 0; it < GNIT; it++) {
        if (it + 3 < GNIT)      { asm volatile("cp.async.wait_group 2;" ::: "memory"); }
        else if (it + 2 < GNIT) { asm volatile("cp.async.wait_group 1;" ::: "memory"); }
        else                    { asm volatile("cp.async.wait_group 0;" ::: "memory"); }
        __syncthreads();
        if (it + 3 < GNIT) prefetch(it + 3);

        const uint32_t base = sb + (it & (NSTAGE - 1)) * STAGE_BYTES;
#pragma unroll
        for (int kk = 0; kk < 2; kk++) {               // two k16 steps per BK=32
            const uint32_t koff = (uint32_t)(kk * 32);  // 16 fp16 = 32 bytes
            uint32_t bhf[4][4], blf[4][4];
#pragma unroll
            for (int p = 0; p < 4; p++) {
                uint32_t bd = base + b_rb + (uint32_t)(p * 16 * ROWB) + koff;
                ldsm_x4(bhf[p], bd + OFF_BH);
                ldsm_x4(blf[p], bd + OFF_BL);
            }
#pragma unroll
            for (int mf = 0; mf < 4; mf++) {
                uint32_t ad = base + a_rb + (uint32_t)(mf * 16 * ROWB) + koff;
                uint32_t af[4];
                ldsm_x4(af, ad + OFF_A);
#pragma unroll
                for (int nf = 0; nf < 8; nf++) {
                    const int p = nf >> 1, o = nf & 1;
                    uint32_t bhv[2] = {bhf[p][o], bhf[p][o + 2]};
                    uint32_t blv[2] = {blf[p][o], blf[p][o + 2]};
                    mma16816h(acc[mf][nf], af, bhv);
                    mma16816h(acc[mf][nf], af, blv);
                }
            }
        }
    }

    // epilogue: direct stores with bias
#pragma unroll
    for (int mf = 0; mf < 4; mf++) {
        const int r0 = m0 + wm * 64 + mf * 16 + (lane >> 2);
#pragma unroll
        for (int nf = 0; nf < 8; nf++) {
            const int col = n0 + wn * 64 + nf * 8 + (lane & 3) * 2;
            const float b0 = bias[col], b1 = bias[col + 1];
            float* p0 = C + (size_t)r0 * N + col;
            float2 v0 = make_float2(acc[mf][nf][0] + b0, acc[mf][nf][1] + b1);
            float2 v1 = make_float2(acc[mf][nf][2] + b0, acc[mf][nf][3] + b1);
            *(float2*)p0 = v0;
            *(float2*)(p0 + 8 * N) = v1;
        }
    }
}

// ---------------- operand preparation ----------------
// activations: fp32 -> single fp16
__global__ void act_f16_kernel(const float* __restrict__ A,
                               __half* __restrict__ H, int n4) {
    int i = blockIdx.x * 256 + threadIdx.x;
    if (i >= n4) return;
    float4 v = *(const float4*)(A + (size_t)i * 4);
    __half h[4] = {__float2half_rn(v.x), __float2half_rn(v.y),
                   __float2half_rn(v.z), __float2half_rn(v.w)};
    *(uint2*)(H + (size_t)i * 4) = *(uint2*)h;
}

// weights: transpose + fp16 hi/lo split: W[K,N] -> Wt_hi/lo[N,K]
__global__ void wtrans_split_kernel(const float* __restrict__ W,
                                    __half* __restrict__ th,
                                    __half* __restrict__ tl, int K, int N) {
    __shared__ float t[32][33];
    int k0 = blockIdx.y * 32, n0 = blockIdx.x * 32;
    int tx = threadIdx.x, ty = threadIdx.y;
#pragma unroll
    for (int i = ty; i < 32; i += 8)
        t[i][tx] = W[(size_t)(k0 + i) * N + n0 + tx];
    __syncthreads();
#pragma unroll
    for (int i = ty; i < 32; i += 8) {
        float v = t[tx][i];
        __half h = __float2half_rn(v);
        size_t o = (size_t)(n0 + i) * K + k0 + tx;
        th[o] = h;
        tl[o] = __float2half_rn(v - __half2float(h));
    }
}

// ---------------- rope cos/sin table ----------------
__global__ void rope_table_kernel() {
    int idx = blockIdx.x * blockDim.x + threadIdx.x;
    if (idx >= Sc * 32) return;
    int t = idx >> 5, j = idx & 31;
    float ex = (float)(2 * j) / 64.0f;
    float invf = 1.0f / powf(10000.0f, ex);
    float ang = (float)t * invf;
    float s, c;
    sincosf(ang, &s, &c);
    g_cos[idx] = c;
    g_sin[idx] = s;
}

// ---------------- fused: elu+rope K on the fly, Mpart = K_rot^T V, Ksum partials ----------------
__global__ __launch_bounds__(256)
void compute_mpart_kernel() {
    const int bh = blockIdx.x, split = blockIdx.y;
    const int b = bh >> 4, h = bh & 15;
    __shared__ float Ksm[32][64];
    __shared__ float Vsm[32][68];
    __shared__ float red[32][64];
    const int tid = threadIdx.x;
    const int ti = tid >> 4, td = tid & 15;
    const int lrow = tid >> 3;                  // 0..31
    const int jc = (tid & 7) * 4;               // pair-col base 0..28

    float acc[4][4];
#pragma unroll
    for (int i = 0; i < 4; i++)
#pragma unroll
        for (int j = 0; j < 4; j++) acc[i][j] = 0.0f;
    float ks1[4] = {0, 0, 0, 0}, ks2[4] = {0, 0, 0, 0};

    for (int kt = 0; kt < 4; kt++) {
        const int s = split * 128 + kt * 32 + lrow;
        const float* kp = &g_KV[(size_t)(b * Sc + s) * 2048 + h * 64];
        float4 k1 = *(const float4*)(kp + jc);
        float4 k2 = *(const float4*)(kp + jc + 32);
        float4 c4 = *(const float4*)&g_cos[s * 32 + jc];
        float4 s4 = *(const float4*)&g_sin[s * 32 + jc];
        float e1[4] = {eluplus(k1.x), eluplus(k1.y), eluplus(k1.z), eluplus(k1.w)};
        float e2[4] = {eluplus(k2.x), eluplus(k2.y), eluplus(k2.z), eluplus(k2.w)};
        float cc[4] = {c4.x, c4.y, c4.z, c4.w};
        float ss[4] = {s4.x, s4.y, s4.z, s4.w};
#pragma unroll
        for (int q = 0; q < 4; q++) {
            Ksm[lrow][jc + q]      = e1[q] * cc[q] - e2[q] * ss[q];
            Ksm[lrow][jc + 32 + q] = e2[q] * cc[q] + e1[q] * ss[q];
            ks1[q] += e1[q];
            ks2[q] += e2[q];
        }
        float4 v1 = *(const float4*)(kp + 1024 + jc);
        float4 v2 = *(const float4*)(kp + 1024 + jc + 32);
        *(float4*)&Vsm[lrow][jc]      = v1;
        *(float4*)&Vsm[lrow][jc + 32] = v2;
        __syncthreads();
#pragma unroll 8
        for (int k = 0; k < 32; k++) {
            float4 a4 = *(const float4*)&Ksm[k][ti * 4];
            float4 b4 = *(const float4*)&Vsm[k][td * 4];
            float a[4] = {a4.x, a4.y, a4.z, a4.w};
            float bb[4] = {b4.x, b4.y, b4.z, b4.w};
#pragma unroll
            for (int i = 0; i < 4; i++)
#pragma unroll
                for (int j = 0; j < 4; j++) acc[i][j] += a[i] * bb[j];
        }
        __syncthreads();
    }

#pragma unroll
    for (int q = 0; q < 4; q++) {
        red[lrow][jc + q]      = ks1[q];
        red[lrow][jc + 32 + q] = ks2[q];
    }
    __syncthreads();
    if (tid < 64) {
        float s = 0.0f;
#pragma unroll
        for (int r = 0; r < 32; r++) s += red[r][tid];
        g_Kpart[split][bh * 64 + tid] = s;
    }

    float* mp = &g_Mpart[split][bh * 4096];
#pragma unroll
    for (int i = 0; i < 4; i++) {
        float4 o = make_float4(acc[i][0], acc[i][1], acc[i][2], acc[i][3]);
        *(float4*)&mp[(ti * 4 + i) * 64 + td * 4] = o;
    }
}

// ---------------- reduce split-K partials (deterministic) ----------------
__global__ void reduce_parts_kernel() {
    int idx = blockIdx.x * 256 + threadIdx.x;
    if (idx < BHc * 4096) {
        float s = 0.0f;
#pragma unroll
        for (int sp = 0; sp < NSPLIT; sp++) s += g_Mpart[sp][idx];
        g_M[idx] = s;
    } else if (idx < BHc * 4096 + BHc * 64) {
        int i2 = idx - BHc * 4096;
        float s = 0.0f;
#pragma unroll
        for (int sp = 0; sp < NSPLIT; sp++) s += g_Kpart[sp][i2];
        g_Ksum[i2] = s;
    }
}

// ---------------- y = (rope(elu(Q)+1) @ M) / (elu(Q)+1 . Ksum) -> fp16 ----------------
// bh_base selects the batch half (0 => b=0 heads, 16 => b=1 heads)
__global__ __launch_bounds__(256)
void compute_y_kernel(int bh_base) {
    const int bh = blockIdx.x + bh_base, tchunk = blockIdx.y;
    const int b = bh >> 4, h = bh & 15;
    const int t0 = tchunk * 64;
    __shared__ float smA[64 * 65];
    __shared__ float qrot[64 * 65];
    __shared__ float ks[64];
    __shared__ float den[64];
    const int tid = threadIdx.x;

    if (tid < 64) ks[tid] = g_Ksum[bh * 64 + tid];

#pragma unroll
    for (int it = 0; it < 4; it++) {
        int idx = tid + it * 256;
        int r = idx >> 4, c4 = (idx & 15) * 4;
        float4 qv = *(const float4*)&g_Q[(size_t)(b * Tc + t0 + r) * 1024 + h * 64 + c4];
        smA[r * 65 + c4 + 0] = eluplus(qv.x);
        smA[r * 65 + c4 + 1] = eluplus(qv.y);
        smA[r * 65 + c4 + 2] = eluplus(qv.z);
        smA[r * 65 + c4 + 3] = eluplus(qv.w);
    }
    __syncthreads();

#pragma unroll
    for (int it = 0; it < 8; it++) {
        int idx = tid + it * 256;
        int r = idx >> 5, j = idx & 31;
        float e1 = smA[r * 65 + j], e2 = smA[r * 65 + j + 32];
        int t = t0 + r;
        float c = g_cos[t * 32 + j], si = g_sin[t * 32 + j];
        qrot[r * 65 + j]      = e1 * c - e2 * si;
        qrot[r * 65 + j + 32] = e2 * c + e1 * si;
    }
    if (tid < 64) {
        float s = 0.0f;
#pragma unroll
        for (int d = 0; d < 64; d++) s += smA[tid * 65 + d] * ks[d];
        den[tid] = s;
    }
    __syncthreads();

#pragma unroll
    for (int it = 0; it < 16; it++) {
        int idx = tid + it * 256;
        smA[idx] = g_M[bh * 4096 + idx];
    }
    __syncthreads();

    const int row = tid >> 2;
    const int dg = (tid & 3) * 16;
    float acc[16];
#pragma unroll
    for (int i = 0; i < 16; i++) acc[i] = 0.0f;
#pragma unroll
    for (int k = 0; k < 64; k++) {
        float qv = qrot[row * 65 + k];
#pragma unroll
        for (int q = 0; q < 4; q++) {
            float4 mv = *(const float4*)&smA[k * 64 + dg + q * 4];
            acc[q * 4 + 0] += qv * mv.x;
            acc[q * 4 + 1] += qv * mv.y;
            acc[q * 4 + 2] += qv * mv.z;
            acc[q * 4 + 3] += qv * mv.w;
        }
    }
    float inv = 1.0f / den[row];
    size_t yoff = (size_t)(b * Tc + t0 + row) * 1024 + h * 64 + dg;
    __half hv[16];
#pragma unroll
    for (int i = 0; i < 16; i++) hv[i] = __float2half_rn(acc[i] * inv);
    *(uint4*)(g_yh + yoff)     = *(uint4*)hv;
    *(uint4*)(g_yh + yoff + 8) = *(uint4*)(hv + 8);
}

// ---------------- launch (multi-stream fork/join inside the captured graph) ----------------
extern "C" void kernel_launch(void* const* d_in, const int* in_sizes, int n_in,
                              void* d_out, int out_size) {
    const float* x      = (const float*)d_in[0];
    const float* memory = (const float*)d_in[1];
    const float* q_w    = (const float*)d_in[2];
    const float* q_b    = (const float*)d_in[3];
    const float* kv_w   = (const float*)d_in[4];
    const float* kv_b   = (const float*)d_in[5];
    const float* proj_w = (const float*)d_in[6];
    const float* proj_b = (const float*)d_in[7];
    float* out = (float*)d_out;

    cudaFuncSetAttribute(tc_gemm, cudaFuncAttributeMaxDynamicSharedMemorySize, SM_TOTAL);

    float *pQ, *pKV;
    cudaGetSymbolAddress((void**)&pQ,  g_Q);
    cudaGetSymbolAddress((void**)&pKV, g_KV);
    __half *xh, *mh, *yh, *kwh, *kwl, *qwh, *qwl, *pwh, *pwl;
    cudaGetSymbolAddress((void**)&xh, g_xh);
    cudaGetSymbolAddress((void**)&mh, g_mh);
    cudaGetSymbolAddress((void**)&yh, g_yh);
    cudaGetSymbolAddress((void**)&kwh, g_kvwt_hi); cudaGetSymbolAddress((void**)&kwl, g_kvwt_lo);
    cudaGetSymbolAddress((void**)&qwh, g_qwt_hi);  cudaGetSymbolAddress((void**)&qwl, g_qwt_lo);
    cudaGetSymbolAddress((void**)&pwh, g_pwt_hi);  cudaGetSymbolAddress((void**)&pwl, g_pwt_lo);

    // one-time host-side infra (stream/event handles; no device memory involved)
    static cudaStream_t s_q = nullptr, s_w = nullptr;
    static cudaEvent_t ev_root = nullptr, ev_q = nullptr, ev_w = nullptr,
                       ev_kvw = nullptr, ev_y0 = nullptr, ev_p0 = nullptr;
    if (s_q == nullptr) {
        cudaStreamCreateWithFlags(&s_q, cudaStreamNonBlocking);
        cudaStreamCreateWithFlags(&s_w, cudaStreamNonBlocking);
        cudaEventCreateWithFlags(&ev_root, cudaEventDisableTiming);
        cudaEventCreateWithFlags(&ev_q,    cudaEventDisableTiming);
        cudaEventCreateWithFlags(&ev_w,    cudaEventDisableTiming);
        cudaEventCreateWithFlags(&ev_kvw,  cudaEventDisableTiming);
        cudaEventCreateWithFlags(&ev_y0,   cudaEventDisableTiming);
        cudaEventCreateWithFlags(&ev_p0,   cudaEventDisableTiming);
    }

    // fork side streams off the origin stream
    cudaEventRecord(ev_root, 0);
    cudaStreamWaitEvent(s_q, ev_root, 0);
    cudaStreamWaitEvent(s_w, ev_root, 0);

    // ---- side stream s_w: rope table + KV/proj weight prep ----
    rope_table_kernel<<<(Sc * 32 + 255) / 256, 256, 0, s_w>>>();
    wtrans_split_kernel<<<dim3(2 * Cc / 32, Cc / 32), dim3(32, 8), 0, s_w>>>(kv_w, kwh, kwl, Cc, 2 * Cc);
    cudaEventRecord(ev_kvw, s_w);                 // rope table + kv weights ready
    wtrans_split_kernel<<<dim3(Cc / 32, Cc / 32), dim3(32, 8), 0, s_w>>>(proj_w, pwh, pwl, Cc, Cc);
    cudaEventRecord(ev_w, s_w);                   // proj weights ready

    // ---- side stream s_q: Q path (independent of KV path) ----
    wtrans_split_kernel<<<dim3(Cc / 32, Cc / 32), dim3(32, 8), 0, s_q>>>(q_w, qwh, qwl, Cc, Cc);
    act_f16_kernel<<<(Bc * Tc * Cc / 4 + 255) / 256, 256, 0, s_q>>>(x, xh, Bc * Tc * Cc / 4);
    tc_gemm<<<dim3(Cc / GBN, Bc * Tc / GBM), 256, SM_TOTAL, s_q>>>(xh, qwh, qwl, q_b, pQ, Cc);
    cudaEventRecord(ev_q, s_q);

    // ---- origin stream: KV critical chain ----
    act_f16_kernel<<<(Bc * Sc * Cc / 4 + 255) / 256, 256>>>(memory, mh, Bc * Sc * Cc / 4);
    cudaStreamWaitEvent(0, ev_kvw, 0);
    tc_gemm<<<dim3(2 * Cc / GBN, Bc * Sc / GBM), 256, SM_TOTAL>>>(mh, kwh, kwl, kv_b, pKV, 2 * Cc);
    compute_mpart_kernel<<<dim3(BHc, NSPLIT), 256>>>();
    reduce_parts_kernel<<<(BHc * 4096 + BHc * 64 + 255) / 256, 256>>>();

    // ---- pipelined attention + proj, split by batch ----
    cudaStreamWaitEvent(0, ev_q, 0);
    // batch 0 attention
    compute_y_kernel<<<dim3(BHc / 2, Tc / 64), 256>>>(0);
    cudaEventRecord(ev_y0, 0);
    // batch 0 proj on s_q (overlaps batch-1 attention on origin)
    cudaStreamWaitEvent(s_q, ev_y0, 0);
    cudaStreamWaitEvent(s_q, ev_w, 0);
    tc_gemm<<<dim3(Cc / GBN, Tc / GBM), 256, SM_TOTAL, s_q>>>(yh, pwh, pwl, proj_b, out, Cc);
    cudaEventRecord(ev_p0, s_q);
    // batch 1 attention + proj on origin
    compute_y_kernel<<<dim3(BHc / 2, Tc / 64), 256>>>(BHc / 2);
    cudaStreamWaitEvent(0, ev_w, 0);
    tc_gemm<<<dim3(Cc / GBN, Tc / GBM), 256, SM_TOTAL>>>(yh + (size_t)Tc * Cc, pwh, pwl,
                                                         proj_b, out + (size_t)Tc * Cc, Cc);
    // join batch-0 proj back into origin
    cudaStreamWaitEvent(0, ev_p0, 0);
}